// round 15
// baseline (speedup 1.0000x reference)
#include <cuda_runtime.h>
#include <cuda_fp16.h>
#include <math.h>
#include <stdint.h>

#define BB 2
#define SS 2048
#define DIM 2048
#define NH 16
#define NKVH 4
#define HD 128
#define WIN 512
#define EPSV 1.1920928955078125e-07f

#define M_TOT (BB*SS)   // 4096
#define KVD (NKVH*HD)   // 512
#define NQKV (DIM + KVD + KVD)  // 3072

#define QSC 0.12752781685914614f
#define EOFF 1.3f
#define WSCALE 32.0f
#define WUNSCALE 0.03125f

// ---------------- scratch ----------------
__device__ float g_qraw[(size_t)M_TOT * DIM];
__device__ float g_kraw[(size_t)M_TOT * KVD];

__device__ __half g_xh[(size_t)M_TOT * DIM];
#define W_ROWS (DIM + KVD + KVD + DIM)   // 5120
__device__ __half g_wh[(size_t)W_ROWS * DIM];
__device__ __half g_wl[(size_t)W_ROWS * DIM];
__device__ __half g_vh[(size_t)M_TOT * KVD];
__device__ __half g_vl[(size_t)M_TOT * KVD];
__device__ __half g_yh[(size_t)M_TOT * DIM];
__device__ __half g_qh[(size_t)BB * NH * SS * HD];
__device__ __half g_kh[(size_t)BB * NKVH * SS * HD];
__device__ __half g_kl[(size_t)BB * NKVH * SS * HD];

// =====================================================================
// helpers
// =====================================================================
__device__ __forceinline__ uint32_t smem_u32(const void* p) {
    uint32_t a;
    asm("{ .reg .u64 t; cvta.to.shared.u64 t, %1; cvt.u32.u64 %0, t; }"
        : "=r"(a) : "l"(p));
    return a;
}
__device__ __forceinline__ void ldsm_x4(uint32_t* r, uint32_t addr) {
    asm volatile("ldmatrix.sync.aligned.m8n8.x4.shared.b16 {%0,%1,%2,%3}, [%4];"
        : "=r"(r[0]), "=r"(r[1]), "=r"(r[2]), "=r"(r[3]) : "r"(addr));
}
__device__ __forceinline__ void ldsm_x4_t(uint32_t* r, uint32_t addr) {
    asm volatile("ldmatrix.sync.aligned.m8n8.x4.trans.shared.b16 {%0,%1,%2,%3}, [%4];"
        : "=r"(r[0]), "=r"(r[1]), "=r"(r[2]), "=r"(r[3]) : "r"(addr));
}
__device__ __forceinline__ void mma_f16(float* c, const uint32_t* a, const uint32_t* b) {
    asm volatile(
        "mma.sync.aligned.m16n8k16.row.col.f32.f16.f16.f32 "
        "{%0,%1,%2,%3}, {%4,%5,%6,%7}, {%8,%9}, {%0,%1,%2,%3};"
        : "+f"(c[0]), "+f"(c[1]), "+f"(c[2]), "+f"(c[3])
        : "r"(a[0]), "r"(a[1]), "r"(a[2]), "r"(a[3]), "r"(b[0]), "r"(b[1]));
}
__device__ __forceinline__ void cp16(uint32_t saddr, const void* gaddr) {
    asm volatile("cp.async.cg.shared.global [%0], [%1], 16;"
                 :: "r"(saddr), "l"(gaddr));
}
__device__ __forceinline__ void cp16z(uint32_t saddr, const void* gaddr, int sz) {
    asm volatile("cp.async.cg.shared.global [%0], [%1], 16, %2;"
                 :: "r"(saddr), "l"(gaddr), "r"(sz));
}
#define CP_COMMIT() asm volatile("cp.async.commit_group;" ::: "memory")
#define CP_WAIT2()  asm volatile("cp.async.wait_group 2;" ::: "memory")
#define CP_WAIT0()  asm volatile("cp.async.wait_group 0;" ::: "memory")

__device__ __forceinline__ uint32_t packh2(float a, float b, float* la, float* lb) {
    __half ha = __float2half_rn(a), hb = __float2half_rn(b);
    *la = a - __half2float(ha);
    *lb = b - __half2float(hb);
    return ((uint32_t)__half_as_ushort(hb) << 16) | __half_as_ushort(ha);
}
__device__ __forceinline__ uint32_t packh2n(float a, float b) {
    return ((uint32_t)__half_as_ushort(__float2half_rn(b)) << 16)
         | __half_as_ushort(__float2half_rn(a));
}

// =====================================================================
// conversions
// =====================================================================
__global__ void __launch_bounds__(256) conv_x_kernel(
    const float4* __restrict__ src, uint2* __restrict__ dst, long n4)
{
    long i = (long)blockIdx.x * blockDim.x + threadIdx.x;
    long stride = (long)gridDim.x * blockDim.x;
    for (; i < n4; i += stride) {
        float4 v = src[i];
        uint2 d;
        d.x = packh2n(v.x, v.y);
        d.y = packh2n(v.z, v.w);
        dst[i] = d;
    }
}

__global__ void __launch_bounds__(256) split_w_all_kernel(
    const float4* __restrict__ Wq, const float4* __restrict__ Wk,
    const float4* __restrict__ Wv, const float4* __restrict__ Wo,
    uint2* __restrict__ hi, uint2* __restrict__ lo)
{
    const long n4 = (long)W_ROWS * DIM / 4;
    const long q1 = (long)DIM * DIM / 4;
    const long q2 = q1 + (long)KVD * DIM / 4;
    const long q3 = q2 + (long)KVD * DIM / 4;
    long i = (long)blockIdx.x * blockDim.x + threadIdx.x;
    long stride = (long)gridDim.x * blockDim.x;
    for (; i < n4; i += stride) {
        float4 v;
        if      (i < q1) v = Wq[i];
        else if (i < q2) v = Wk[i - q1];
        else if (i < q3) v = Wv[i - q2];
        else             v = Wo[i - q3];
        float ax = v.x * WSCALE, ay = v.y * WSCALE,
              az = v.z * WSCALE, aw = v.w * WSCALE;
        float lx, ly, lz, lw;
        uint2 h;
        h.x = packh2(ax, ay, &lx, &ly);
        h.y = packh2(az, aw, &lz, &lw);
        hi[i] = h;
        uint2 l;
        l.x = packh2n(lx, ly);
        l.y = packh2n(lz, lw);
        lo[i] = l;
    }
}

// =====================================================================
// GEMM core (fp16). TWOC uniform per CTA.
// =====================================================================
#define SROW 40
#define TILE_BYTES (128 * SROW * 2)      // 10240
#define STAGE3 (3 * TILE_BYTES)
#define GEMM_SMEM (3 * STAGE3)           // 92160

#define GEMM_BODY(Ah_, Bh_, Bl_, Kdim, TWOC)                                  \
    const int tid  = threadIdx.x;                                             \
    const int wid  = tid >> 5;                                                \
    const int lane = tid & 31;                                                \
    const int wm   = wid & 3;                                                 \
    const int wn   = wid >> 2;                                                \
    const int bm   = blockIdx.y * 128;                                        \
    const int bn   = blockIdx.x * 128;                                        \
    const __half* Ah = (Ah_) + (size_t)bm * (Kdim);                           \
    const __half* Bh = (Bh_) + (size_t)bn * (Kdim);                           \
    const __half* Bl = (Bl_) + (size_t)bn * (Kdim);                           \
    const int l_row0 = tid >> 2;                                              \
    const int l_row1 = (tid + 256) >> 2;                                      \
    const int l_ch   = (tid & 3) * 8;                                         \
    const uint32_t s_off0 = (uint32_t)(l_row0 * SROW + l_ch) * 2;             \
    const uint32_t s_off1 = (uint32_t)(l_row1 * SROW + l_ch) * 2;             \
    auto issue = [&](int stage, int kc) {                                     \
        uint32_t sb = smb + stage * STAGE3;                                   \
        cp16(sb + 0 * TILE_BYTES + s_off0, Ah + (size_t)l_row0 * (Kdim) + kc + l_ch); \
        cp16(sb + 0 * TILE_BYTES + s_off1, Ah + (size_t)l_row1 * (Kdim) + kc + l_ch); \
        cp16(sb + 1 * TILE_BYTES + s_off0, Bh + (size_t)l_row0 * (Kdim) + kc + l_ch); \
        cp16(sb + 1 * TILE_BYTES + s_off1, Bh + (size_t)l_row1 * (Kdim) + kc + l_ch); \
        if (TWOC) {                                                           \
            cp16(sb + 2 * TILE_BYTES + s_off0, Bl + (size_t)l_row0 * (Kdim) + kc + l_ch); \
            cp16(sb + 2 * TILE_BYTES + s_off1, Bl + (size_t)l_row1 * (Kdim) + kc + l_ch); \
        }                                                                     \
    };                                                                        \
    float acc[2][8][4];                                                       \
    _Pragma("unroll")                                                         \
    for (int mt = 0; mt < 2; mt++)                                            \
        _Pragma("unroll")                                                     \
        for (int nt = 0; nt < 8; nt++)                                        \
            _Pragma("unroll")                                                 \
            for (int r = 0; r < 4; r++) acc[mt][nt][r] = 0.f;                 \
    const int a_mrow = lane & 15;                                             \
    const int a_koff = (lane >> 4) << 3;                                      \
    const int b_row4 = (lane & 7) + ((lane >> 4) & 1) * 8;                    \
    const int b_koff = ((lane >> 3) & 1) << 3;                                \
    const int NC = (Kdim) >> 5;                                               \
    issue(0, 0);  CP_COMMIT();                                                \
    issue(1, 32); CP_COMMIT();                                                \
    issue(2, 64); CP_COMMIT();                                                \
    int stage = 0;                                                            \
    for (int c = 0; c < NC; c++) {                                            \
        CP_WAIT2();                                                           \
        __syncthreads();                                                      \
        const uint32_t sb = smb + stage * STAGE3;                             \
        _Pragma("unroll")                                                     \
        for (int ks = 0; ks < 2; ks++) {                                      \
            uint32_t ah[2][4];                                                \
            _Pragma("unroll")                                                 \
            for (int mt = 0; mt < 2; mt++) {                                  \
                uint32_t ar = (uint32_t)((wm * 32 + mt * 16 + a_mrow) * SROW  \
                                         + ks * 16 + a_koff) * 2;             \
                ldsm_x4(ah[mt], sb + 0 * TILE_BYTES + ar);                    \
            }                                                                 \
            _Pragma("unroll")                                                 \
            for (int nt2 = 0; nt2 < 4; nt2++) {                               \
                uint32_t br = (uint32_t)((wn * 64 + nt2 * 16 + b_row4) * SROW \
                                         + ks * 16 + b_koff) * 2;             \
                uint32_t bh[4], bl[4];                                        \
                ldsm_x4(bh, sb + 1 * TILE_BYTES + br);                        \
                if (TWOC) ldsm_x4(bl, sb + 2 * TILE_BYTES + br);              \
                _Pragma("unroll")                                             \
                for (int sub = 0; sub < 2; sub++) {                           \
                    _Pragma("unroll")                                         \
                    for (int mt = 0; mt < 2; mt++) {                          \
                        float* a4 = acc[mt][nt2 * 2 + sub];                   \
                        mma_f16(a4, ah[mt], &bh[sub * 2]);                    \
                        if (TWOC) mma_f16(a4, ah[mt], &bl[sub * 2]);          \
                    }                                                         \
                }                                                             \
            }                                                                 \
        }                                                                     \
        __syncthreads();                                                      \
        if (c + 3 < NC) issue(stage, (c + 3) << 5);                           \
        CP_COMMIT();                                                          \
        stage = (stage == 2) ? 0 : stage + 1;                                 \
    }

// =====================================================================
// Fused QKV GEMM: Q/K 1-chain, V 2-chain.
// =====================================================================
__global__ void __launch_bounds__(256, 2) gemm_qkv_kernel()
{
    extern __shared__ char smc[];
    const uint32_t smb = smem_u32(smc);
    const bool twoc = (blockIdx.x >= (DIM + KVD) / 128);

    GEMM_BODY(g_xh, g_wh, g_wl, DIM, twoc)

    const int gp = lane >> 2, t4 = lane & 3;
#pragma unroll
    for (int mt = 0; mt < 2; mt++) {
#pragma unroll
        for (int nt = 0; nt < 8; nt++) {
            int row  = bm + wm * 32 + mt * 16 + gp;
            int gcol = bn + wn * 64 + nt * 8 + t4 * 2;
            float c0 = acc[mt][nt][0] * WUNSCALE, c1 = acc[mt][nt][1] * WUNSCALE;
            float c2 = acc[mt][nt][2] * WUNSCALE, c3 = acc[mt][nt][3] * WUNSCALE;
            if (gcol < DIM) {
                *(float2*)&g_qraw[(size_t)row * DIM + gcol]       = make_float2(c0, c1);
                *(float2*)&g_qraw[(size_t)(row + 8) * DIM + gcol] = make_float2(c2, c3);
            } else if (gcol < DIM + KVD) {
                int cc = gcol - DIM;
                *(float2*)&g_kraw[(size_t)row * KVD + cc]       = make_float2(c0, c1);
                *(float2*)&g_kraw[(size_t)(row + 8) * KVD + cc] = make_float2(c2, c3);
            } else {
                int cc = gcol - DIM - KVD;
                float l0, l1;
                uint32_t h = packh2(c0, c1, &l0, &l1);
                *(uint32_t*)&g_vh[(size_t)row * KVD + cc] = h;
                *(uint32_t*)&g_vl[(size_t)row * KVD + cc] = packh2n(l0, l1);
                h = packh2(c2, c3, &l0, &l1);
                *(uint32_t*)&g_vh[(size_t)(row + 8) * KVD + cc] = h;
                *(uint32_t*)&g_vl[(size_t)(row + 8) * KVD + cc] = packh2n(l0, l1);
            }
        }
    }
}

// =====================================================================
// Wo GEMM (1-chain)
// =====================================================================
__global__ void __launch_bounds__(256, 2) gemm_wo_kernel(
    const __half* __restrict__ Bhp, float* __restrict__ C)
{
    extern __shared__ char smc[];
    const uint32_t smb = smem_u32(smc);

    GEMM_BODY(g_yh, Bhp, Bhp, DIM, false)

    const int gp = lane >> 2, t4 = lane & 3;
#pragma unroll
    for (int mt = 0; mt < 2; mt++) {
#pragma unroll
        for (int nt = 0; nt < 8; nt++) {
            int row = bm + wm * 32 + mt * 16 + gp;
            int col = bn + wn * 64 + nt * 8 + t4 * 2;
            *(float2*)&C[(size_t)row * DIM + col] =
                make_float2(acc[mt][nt][0] * WUNSCALE, acc[mt][nt][1] * WUNSCALE);
            *(float2*)&C[(size_t)(row + 8) * DIM + col] =
                make_float2(acc[mt][nt][2] * WUNSCALE, acc[mt][nt][3] * WUNSCALE);
        }
    }
}

// =====================================================================
// Fused RMSNorm + RoPE
// =====================================================================
__global__ void __launch_bounds__(128) normrope_kernel(const float* __restrict__ q_gain)
{
    const int bs = blockIdx.x;
    const int b  = bs >> 11;
    const int s  = bs & (SS - 1);
    const int hh = blockIdx.y;
    const int i  = threadIdx.x;
    const bool isq = (hh < NH);

    const float* src = isq
        ? &g_qraw[((size_t)bs * NH + hh) * HD]
        : &g_kraw[((size_t)bs * NKVH + (hh - NH)) * HD];

    float v = src[i];

    float ss = v * v;
#pragma unroll
    for (int o = 16; o > 0; o >>= 1) ss += __shfl_xor_sync(0xffffffffu, ss, o);
    __shared__ float wsum[4];
    if ((i & 31) == 0) wsum[i >> 5] = ss;
    __syncthreads();
    float tot = wsum[0] + wsum[1] + wsum[2] + wsum[3];
    float rn = rsqrtf(tot * (1.0f / HD) + EPSV);

    __shared__ float sh[HD];
    sh[i] = v * rn;
    __syncthreads();

    const int ii = i & 63;
    double inv_freq = pow(10000.0, -(double)ii / 64.0);
    double cd, sd;
    sincos((double)s * inv_freq, &cd, &sd);
    const float c = (float)cd, sn = (float)sd;

    float x1 = sh[ii], x2 = sh[ii + 64];
    float outv = (i < 64) ? (x1 * c - x2 * sn) : (x1 * sn + x2 * c);

    if (isq) {
        outv *= q_gain[hh] * QSC;
        g_qh[(((size_t)b * NH + hh) * SS + s) * HD + i] = __float2half_rn(outv);
    } else {
        size_t o = (((size_t)b * NKVH + (hh - NH)) * SS + s) * HD + i;
        __half h = __float2half_rn(outv);
        g_kh[o] = h;
        g_kl[o] = __float2half_rn(outv - __half2float(h));
    }
}

// =====================================================================
// Flash sliding-window attention (byte-identical to R14)
// =====================================================================
#define AQSTR 136
#define APSTR 72
#define AQ  0
#define AKH (64 * AQSTR)
#define AKL (2 * 64 * AQSTR)
#define AVH (3 * 64 * AQSTR)
#define AVL (4 * 64 * AQSTR)
#define AP  (5 * 64 * AQSTR)
#define ATTN_SMEM_BYTES ((AP + 64 * APSTR) * 2)   // 96256

__global__ void __launch_bounds__(256, 2) attn_kernel()
{
    extern __shared__ __half sma[];
    const uint32_t smb = smem_u32(sma);
    __shared__ float rowsumP[64][4];
    __shared__ float rinv[64];

    const int tid  = threadIdx.x;
    const int wid  = tid >> 5;
    const int lane = tid & 31;
    const int wm   = wid & 1;
    const int wn   = wid >> 1;
    const int gp   = lane >> 2;
    const int t4   = lane & 3;

    const int qt  = blockIdx.x;
    const int h   = blockIdx.y;
    const int b   = blockIdx.z;
    const int kvh = h >> 2;
    const int qs0 = qt * 64;
    const int t0  = max(0, qs0 - (WIN - 1));
    const int L   = qs0 + 64 - t0;
    const int nchunks = (L + 63) >> 6;

    const __half* Qh = g_qh + (((size_t)b * NH + h) * SS + qs0) * HD;
    const __half* Kh = g_kh + ((size_t)b * NKVH + kvh) * SS * HD;
    const __half* Kl = g_kl + ((size_t)b * NKVH + kvh) * SS * HD;
    const __half* Vh = g_vh + ((size_t)(b * SS)) * KVD + kvh * HD;
    const __half* Vl = g_vl + ((size_t)(b * SS)) * KVD + kvh * HD;

#pragma unroll
    for (int it = 0; it < 4; it++) {
        int idx = tid + it * 256;
        int row = idx >> 4;
        int h8  = (idx & 15) * 8;
        *(uint4*)&sma[AQ + row * AQSTR + h8] = *(const uint4*)&Qh[(size_t)row * HD + h8];
    }
    rowsumP[tid >> 2][tid & 3] = 0.f;

    auto issueK = [&](int kt) {
#pragma unroll
        for (int it = 0; it < 4; it++) {
            int idx = tid + it * 256;
            int n   = idx >> 4;
            int h8  = (idx & 15) * 8;
            int j   = kt + n;
            int sz  = (j < L) ? 16 : 0;
            int jc  = (j < L) ? j : 0;
            cp16z(smb + (AKH + n * AQSTR + h8) * 2, Kh + (size_t)(t0 + jc) * HD + h8, sz);
            cp16z(smb + (AKL + n * AQSTR + h8) * 2, Kl + (size_t)(t0 + jc) * HD + h8, sz);
        }
    };
    auto issueV = [&](int kt) {
#pragma unroll
        for (int it = 0; it < 4; it++) {
            int idx = tid + it * 256;
            int n   = idx >> 4;
            int h8  = (idx & 15) * 8;
            int j   = kt + n;
            int sz  = (j < L) ? 16 : 0;
            int jc  = (j < L) ? j : 0;
            cp16z(smb + (AVH + n * AQSTR + h8) * 2, Vh + (size_t)(t0 + jc) * KVD + h8, sz);
            cp16z(smb + (AVL + n * AQSTR + h8) * 2, Vl + (size_t)(t0 + jc) * KVD + h8, sz);
        }
    };

    issueK(0);
    CP_COMMIT();

    float oacc[2][4][4];
#pragma unroll
    for (int mt = 0; mt < 2; mt++)
#pragma unroll
        for (int nt = 0; nt < 4; nt++)
#pragma unroll
            for (int r = 0; r < 4; r++) oacc[mt][nt][r] = 0.f;

    const int a_mrow = lane & 15;
    const int a_koff = (lane >> 4) << 3;
    const int b_row4 = (lane & 7) + ((lane >> 4) & 1) * 8;
    const int b_koff = ((lane >> 3) & 1) << 3;
    const int v_trow = ((lane >> 3) & 1) * 8 + (lane & 7);
    const int v_tcol = ((lane >> 4) & 1) * 8;

    for (int ck = 0; ck < nchunks; ck++) {
        const int kt = ck * 64;

        CP_WAIT0();
        __syncthreads();
        issueV(kt);
        CP_COMMIT();

        float sc[2][2][4];
#pragma unroll
        for (int mt = 0; mt < 2; mt++)
#pragma unroll
            for (int nt = 0; nt < 2; nt++)
#pragma unroll
                for (int r = 0; r < 4; r++) sc[mt][nt][r] = 0.f;

#pragma unroll
        for (int ks = 0; ks < 8; ks++) {
            uint32_t ah[2][4];
#pragma unroll
            for (int mt = 0; mt < 2; mt++)
                ldsm_x4(ah[mt], smb + (AQ + (wm * 32 + mt * 16 + a_mrow) * AQSTR
                                       + ks * 16 + a_koff) * 2);
            uint32_t bh[4], bl[4];
            uint32_t br = smb + (AKH + (wn * 16 + b_row4) * AQSTR
                                 + ks * 16 + b_koff) * 2;
            ldsm_x4(bh, br);
            ldsm_x4(bl, br + (AKL - AKH) * 2);
#pragma unroll
            for (int nt = 0; nt < 2; nt++)
#pragma unroll
                for (int mt = 0; mt < 2; mt++) {
                    mma_f16(sc[mt][nt], ah[mt], &bh[nt * 2]);
                    mma_f16(sc[mt][nt], ah[mt], &bl[nt * 2]);
                }
        }

        CP_WAIT0();
        __syncthreads();
        if (ck + 1 < nchunks) issueK(kt + 64);
        CP_COMMIT();

#pragma unroll
        for (int mt = 0; mt < 2; mt++) {
            const int r0l = wm * 32 + mt * 16 + gp;
            const int r0  = qs0 + r0l;
            float rs0 = 0.f, rs1 = 0.f;
#pragma unroll
            for (int nt = 0; nt < 2; nt++) {
                int jl = wn * 16 + nt * 8 + t4 * 2;
                int tg = t0 + kt + jl;
                bool in0 = (kt + jl) < L, in1 = (kt + jl + 1) < L;
                float e0 = (in0 && tg <= r0 && tg + WIN > r0)
                               ? exp2f(sc[mt][nt][0] - EOFF) : 0.f;
                float e1 = (in1 && tg + 1 <= r0 && tg + 1 + WIN > r0)
                               ? exp2f(sc[mt][nt][1] - EOFF) : 0.f;
                float e2 = (in0 && tg <= r0 + 8 && tg + WIN > r0 + 8)
                               ? exp2f(sc[mt][nt][2] - EOFF) : 0.f;
                float e3 = (in1 && tg + 1 <= r0 + 8 && tg + 1 + WIN > r0 + 8)
                               ? exp2f(sc[mt][nt][3] - EOFF) : 0.f;
                *(uint32_t*)&sma[AP + r0l * APSTR + jl]       = packh2n(e0, e1);
                *(uint32_t*)&sma[AP + (r0l + 8) * APSTR + jl] = packh2n(e2, e3);
                rs0 += e0 + e1;
                rs1 += e2 + e3;
            }
            rs0 += __shfl_xor_sync(0xffffffffu, rs0, 1);
            rs0 += __shfl_xor_sync(0xffffffffu, rs0, 2);
            rs1 += __shfl_xor_sync(0xffffffffu, rs1, 1);
            rs1 += __shfl_xor_sync(0xffffffffu, rs1, 2);
            if (t4 == 0) {
                rowsumP[r0l][wn]     += rs0;
                rowsumP[r0l + 8][wn] += rs1;
            }
        }
        __syncthreads();

#pragma unroll
        for (int ks2 = 0; ks2 < 4; ks2++) {
            uint32_t ph[2][4];
#pragma unroll
            for (int mt = 0; mt < 2; mt++)
                ldsm_x4(ph[mt], smb + (AP + (wm * 32 + mt * 16 + a_mrow) * APSTR
                                       + ks2 * 16 + a_koff) * 2);
#pragma unroll
            for (int vt2 = 0; vt2 < 2; vt2++) {
                uint32_t vr = smb + (AVH + (ks2 * 16 + v_trow) * AQSTR
                                     + wn * 32 + vt2 * 16 + v_tcol) * 2;
                uint32_t vh4[4], vl4[4];
                ldsm_x4_t(vh4, vr);
                ldsm_x4_t(vl4, vr + (AVL - AVH) * 2);
#pragma unroll
                for (int sub = 0; sub < 2; sub++)
#pragma unroll
                    for (int mt = 0; mt < 2; mt++) {
                        float* a4 = oacc[mt][vt2 * 2 + sub];
                        mma_f16(a4, ph[mt], &vh4[sub * 2]);
                        mma_f16(a4, ph[mt], &vl4[sub * 2]);
                    }
            }
        }
    }
    __syncthreads();

    if (tid < 64)
        rinv[tid] = 1.0f / (rowsumP[tid][0] + rowsumP[tid][1] +
                            rowsumP[tid][2] + rowsumP[tid][3]);
    __syncthreads();

#pragma unroll
    for (int mt = 0; mt < 2; mt++) {
        const int r0l = wm * 32 + mt * 16 + gp;
        const float ri0 = rinv[r0l];
        const float ri1 = rinv[r0l + 8];
#pragma unroll
        for (int nt = 0; nt < 4; nt++) {
            int d = wn * 32 + nt * 8 + t4 * 2;
            size_t y0 = ((size_t)(b * SS + qs0 + r0l) * NH + h) * HD + d;
            size_t y1 = ((size_t)(b * SS + qs0 + r0l + 8) * NH + h) * HD + d;
            *(uint32_t*)&g_yh[y0] = packh2n(oacc[mt][nt][0] * ri0, oacc[mt][nt][1] * ri0);
            *(uint32_t*)&g_yh[y1] = packh2n(oacc[mt][nt][2] * ri1, oacc[mt][nt][3] * ri1);
        }
    }
}

// =====================================================================
// launch — MEASUREMENT ROUND: attn_kernel launched 4x (idempotent).
// dur = base + 3*T_attn; kernels byte-identical to R14 otherwise.
// =====================================================================
extern "C" void kernel_launch(void* const* d_in, const int* in_sizes, int n_in,
                              void* d_out, int out_size)
{
    float* out = (float*)d_out;

    const float* x  = nullptr;
    const float* qg = nullptr;
    const float* big[2] = {nullptr, nullptr};
    const float* kv [2] = {nullptr, nullptr};
    int nb = 0, nk = 0;

    for (int i = 0; i < n_in; i++) {
        long s = in_sizes[i];
        const float* p = (const float*)d_in[i];
        if      (s == (long)BB * SS * DIM)        x = p;
        else if (s == (long)DIM * DIM)            { if (nb < 2) big[nb++] = p; }
        else if (s == (long)KVD * DIM)            { if (nk < 2) kv[nk++] = p; }
        else if (s == (long)NH)                   qg = p;
    }
    const float* Wq = big[0];
    const float* Wo = big[1];
    const float* Wk = kv[0];
    const float* Wv = kv[1];

    __half *xh, *wh, *wl;
    cudaGetSymbolAddress((void**)&xh, g_xh);
    cudaGetSymbolAddress((void**)&wh, g_wh);
    cudaGetSymbolAddress((void**)&wl, g_wl);

    cudaFuncSetAttribute(gemm_qkv_kernel,
                         cudaFuncAttributeMaxDynamicSharedMemorySize, GEMM_SMEM);
    cudaFuncSetAttribute(gemm_wo_kernel,
                         cudaFuncAttributeMaxDynamicSharedMemorySize, GEMM_SMEM);
    cudaFuncSetAttribute(attn_kernel,
                         cudaFuncAttributeMaxDynamicSharedMemorySize, ATTN_SMEM_BYTES);

    const size_t off_o = (size_t)(DIM + KVD + KVD) * DIM;

    conv_x_kernel<<<4096, 256>>>((const float4*)x, (uint2*)xh, (long)M_TOT * DIM / 4);
    split_w_all_kernel<<<4096, 256>>>((const float4*)Wq, (const float4*)Wk,
                                      (const float4*)Wv, (const float4*)Wo,
                                      (uint2*)wh, (uint2*)wl);

    gemm_qkv_kernel<<<dim3(NQKV / 128, M_TOT / 128), 256, GEMM_SMEM>>>();

    normrope_kernel<<<dim3(BB * SS, NH + NKVH), 128>>>(qg);

    // attention x4 — idempotent; dur delta = 3 * T_attn
    attn_kernel<<<dim3(SS / 64, NH, BB), 256, ATTN_SMEM_BYTES>>>();
    attn_kernel<<<dim3(SS / 64, NH, BB), 256, ATTN_SMEM_BYTES>>>();
    attn_kernel<<<dim3(SS / 64, NH, BB), 256, ATTN_SMEM_BYTES>>>();
    attn_kernel<<<dim3(SS / 64, NH, BB), 256, ATTN_SMEM_BYTES>>>();

    gemm_wo_kernel<<<dim3(DIM / 128, M_TOT / 128), 256, GEMM_SMEM>>>(
        wh + off_o, out);
}

// round 16
// speedup vs baseline: 1.1410x; 1.1410x over previous
#include <cuda_runtime.h>
#include <cuda_fp16.h>
#include <math.h>
#include <stdint.h>

#define BB 2
#define SS 2048
#define DIM 2048
#define NH 16
#define NKVH 4
#define HD 128
#define WIN 512
#define EPSV 1.1920928955078125e-07f

#define M_TOT (BB*SS)   // 4096
#define KVD (NKVH*HD)   // 512
#define NQKV (DIM + KVD + KVD)  // 3072

#define QSC 0.12752781685914614f
#define EOFF 1.3f
#define WSCALE 32.0f
#define WUNSCALE 0.03125f

// ---------------- scratch ----------------
__device__ float g_qraw[(size_t)M_TOT * DIM];
__device__ float g_kraw[(size_t)M_TOT * KVD];

__device__ __half g_xh[(size_t)M_TOT * DIM];
#define W_ROWS (DIM + KVD + KVD + DIM)   // 5120
__device__ __half g_wh[(size_t)W_ROWS * DIM];
__device__ __half g_wl[(size_t)W_ROWS * DIM];
__device__ __half g_vh[(size_t)M_TOT * KVD];
__device__ __half g_vl[(size_t)M_TOT * KVD];
__device__ __half g_yh[(size_t)M_TOT * DIM];
__device__ __half g_qh[(size_t)BB * NH * SS * HD];
__device__ __half g_kh[(size_t)BB * NKVH * SS * HD];
__device__ __half g_kl[(size_t)BB * NKVH * SS * HD];

// =====================================================================
// helpers
// =====================================================================
__device__ __forceinline__ uint32_t smem_u32(const void* p) {
    uint32_t a;
    asm("{ .reg .u64 t; cvta.to.shared.u64 t, %1; cvt.u32.u64 %0, t; }"
        : "=r"(a) : "l"(p));
    return a;
}
__device__ __forceinline__ void ldsm_x4(uint32_t* r, uint32_t addr) {
    asm volatile("ldmatrix.sync.aligned.m8n8.x4.shared.b16 {%0,%1,%2,%3}, [%4];"
        : "=r"(r[0]), "=r"(r[1]), "=r"(r[2]), "=r"(r[3]) : "r"(addr));
}
__device__ __forceinline__ void ldsm_x4_t(uint32_t* r, uint32_t addr) {
    asm volatile("ldmatrix.sync.aligned.m8n8.x4.trans.shared.b16 {%0,%1,%2,%3}, [%4];"
        : "=r"(r[0]), "=r"(r[1]), "=r"(r[2]), "=r"(r[3]) : "r"(addr));
}
__device__ __forceinline__ void mma_f16(float* c, const uint32_t* a, const uint32_t* b) {
    asm volatile(
        "mma.sync.aligned.m16n8k16.row.col.f32.f16.f16.f32 "
        "{%0,%1,%2,%3}, {%4,%5,%6,%7}, {%8,%9}, {%0,%1,%2,%3};"
        : "+f"(c[0]), "+f"(c[1]), "+f"(c[2]), "+f"(c[3])
        : "r"(a[0]), "r"(a[1]), "r"(a[2]), "r"(a[3]), "r"(b[0]), "r"(b[1]));
}
__device__ __forceinline__ void cp16(uint32_t saddr, const void* gaddr) {
    asm volatile("cp.async.cg.shared.global [%0], [%1], 16;"
                 :: "r"(saddr), "l"(gaddr));
}
__device__ __forceinline__ void cp16z(uint32_t saddr, const void* gaddr, int sz) {
    asm volatile("cp.async.cg.shared.global [%0], [%1], 16, %2;"
                 :: "r"(saddr), "l"(gaddr), "r"(sz));
}
#define CP_COMMIT() asm volatile("cp.async.commit_group;" ::: "memory")
#define CP_WAIT1()  asm volatile("cp.async.wait_group 1;" ::: "memory")
#define CP_WAIT0()  asm volatile("cp.async.wait_group 0;" ::: "memory")

__device__ __forceinline__ uint32_t packh2(float a, float b, float* la, float* lb) {
    __half ha = __float2half_rn(a), hb = __float2half_rn(b);
    *la = a - __half2float(ha);
    *lb = b - __half2float(hb);
    return ((uint32_t)__half_as_ushort(hb) << 16) | __half_as_ushort(ha);
}
__device__ __forceinline__ uint32_t packh2n(float a, float b) {
    return ((uint32_t)__half_as_ushort(__float2half_rn(b)) << 16)
         | __half_as_ushort(__float2half_rn(a));
}

// =====================================================================
// conversions
// =====================================================================
__global__ void __launch_bounds__(256) conv_x_kernel(
    const float4* __restrict__ src, uint2* __restrict__ dst, long n4)
{
    long i = (long)blockIdx.x * blockDim.x + threadIdx.x;
    long stride = (long)gridDim.x * blockDim.x;
    for (; i < n4; i += stride) {
        float4 v = src[i];
        uint2 d;
        d.x = packh2n(v.x, v.y);
        d.y = packh2n(v.z, v.w);
        dst[i] = d;
    }
}

__global__ void __launch_bounds__(256) split_w_all_kernel(
    const float4* __restrict__ Wq, const float4* __restrict__ Wk,
    const float4* __restrict__ Wv, const float4* __restrict__ Wo,
    uint2* __restrict__ hi, uint2* __restrict__ lo)
{
    const long n4 = (long)W_ROWS * DIM / 4;
    const long q1 = (long)DIM * DIM / 4;
    const long q2 = q1 + (long)KVD * DIM / 4;
    const long q3 = q2 + (long)KVD * DIM / 4;
    long i = (long)blockIdx.x * blockDim.x + threadIdx.x;
    long stride = (long)gridDim.x * blockDim.x;
    for (; i < n4; i += stride) {
        float4 v;
        if      (i < q1) v = Wq[i];
        else if (i < q2) v = Wk[i - q1];
        else if (i < q3) v = Wv[i - q2];
        else             v = Wo[i - q3];
        float ax = v.x * WSCALE, ay = v.y * WSCALE,
              az = v.z * WSCALE, aw = v.w * WSCALE;
        float lx, ly, lz, lw;
        uint2 h;
        h.x = packh2(ax, ay, &lx, &ly);
        h.y = packh2(az, aw, &lz, &lw);
        hi[i] = h;
        uint2 l;
        l.x = packh2n(lx, ly);
        l.y = packh2n(lz, lw);
        lo[i] = l;
    }
}

// =====================================================================
// GEMM core (fp16), BK=64, 3 stages, ONE sync per iteration.
// TWOC uniform per CTA: true -> A_hi*(B_hi+B_lo), false -> A_hi*B_hi.
// CTA 128x128, 8 warps (4x2).
// =====================================================================
#define SROW 72                           // 64 halves + 8 pad
#define TILE_BYTES (128 * SROW * 2)       // 18432
#define STAGE3 (3 * TILE_BYTES)           // 55296
#define GEMM_SMEM (3 * STAGE3)            // 165888

#define GEMM_BODY(Ah_, Bh_, Bl_, Kdim, TWOC)                                  \
    const int tid  = threadIdx.x;                                             \
    const int wid  = tid >> 5;                                                \
    const int lane = tid & 31;                                                \
    const int wm   = wid & 3;                                                 \
    const int wn   = wid >> 2;                                                \
    const int bm   = blockIdx.y * 128;                                        \
    const int bn   = blockIdx.x * 128;                                        \
    const __half* Ah = (Ah_) + (size_t)bm * (Kdim);                           \
    const __half* Bh = (Bh_) + (size_t)bn * (Kdim);                           \
    const __half* Bl = (Bl_) + (size_t)bn * (Kdim);                           \
    const int l_row = tid >> 3;              /* 0..31, +32 per it */          \
    const int l_ch  = (tid & 7) * 8;         /* 0..56 */                      \
    auto issue = [&](int stg, int kc) {                                       \
        uint32_t sb = smb + stg * STAGE3;                                     \
        _Pragma("unroll")                                                     \
        for (int it = 0; it < 4; it++) {                                      \
            int row = l_row + it * 32;                                        \
            uint32_t off = (uint32_t)(row * SROW + l_ch) * 2;                 \
            cp16(sb + 0 * TILE_BYTES + off, Ah + (size_t)row * (Kdim) + kc + l_ch); \
            cp16(sb + 1 * TILE_BYTES + off, Bh + (size_t)row * (Kdim) + kc + l_ch); \
            if (TWOC)                                                         \
                cp16(sb + 2 * TILE_BYTES + off, Bl + (size_t)row * (Kdim) + kc + l_ch); \
        }                                                                     \
    };                                                                        \
    float acc[2][8][4];                                                       \
    _Pragma("unroll")                                                         \
    for (int mt = 0; mt < 2; mt++)                                            \
        _Pragma("unroll")                                                     \
        for (int nt = 0; nt < 8; nt++)                                        \
            _Pragma("unroll")                                                 \
            for (int r = 0; r < 4; r++) acc[mt][nt][r] = 0.f;                 \
    const int a_mrow = lane & 15;                                             \
    const int a_koff = (lane >> 4) << 3;                                      \
    const int b_row4 = (lane & 7) + ((lane >> 4) & 1) * 8;                    \
    const int b_koff = ((lane >> 3) & 1) << 3;                                \
    const int NC = (Kdim) >> 6;                                               \
    issue(0, 0);  CP_COMMIT();                                                \
    issue(1, 64); CP_COMMIT();                                                \
    int stage = 0;                                                            \
    for (int c = 0; c < NC; c++) {                                            \
        CP_WAIT1();                                                           \
        __syncthreads();                                                      \
        const uint32_t sb = smb + stage * STAGE3;                             \
        _Pragma("unroll")                                                     \
        for (int ks = 0; ks < 4; ks++) {                                      \
            uint32_t ah[2][4];                                                \
            _Pragma("unroll")                                                 \
            for (int mt = 0; mt < 2; mt++) {                                  \
                uint32_t ar = (uint32_t)((wm * 32 + mt * 16 + a_mrow) * SROW  \
                                         + ks * 16 + a_koff) * 2;             \
                ldsm_x4(ah[mt], sb + 0 * TILE_BYTES + ar);                    \
            }                                                                 \
            _Pragma("unroll")                                                 \
            for (int nt2 = 0; nt2 < 4; nt2++) {                               \
                uint32_t br = (uint32_t)((wn * 64 + nt2 * 16 + b_row4) * SROW \
                                         + ks * 16 + b_koff) * 2;             \
                uint32_t bh[4], bl[4];                                        \
                ldsm_x4(bh, sb + 1 * TILE_BYTES + br);                        \
                if (TWOC) ldsm_x4(bl, sb + 2 * TILE_BYTES + br);              \
                _Pragma("unroll")                                             \
                for (int sub = 0; sub < 2; sub++) {                           \
                    _Pragma("unroll")                                         \
                    for (int mt = 0; mt < 2; mt++) {                          \
                        float* a4 = acc[mt][nt2 * 2 + sub];                   \
                        mma_f16(a4, ah[mt], &bh[sub * 2]);                    \
                        if (TWOC) mma_f16(a4, ah[mt], &bl[sub * 2]);          \
                    }                                                         \
                }                                                             \
            }                                                                 \
        }                                                                     \
        /* issue chunk c+2 into buffer (c+2)%3 == (c-1)%3: its reads      */  \
        /* finished in iter c-1, before this iter's top __syncthreads.    */  \
        if (c + 2 < NC) issue((c + 2) % 3, (c + 2) << 6);                     \
        CP_COMMIT();                                                          \
        stage = (stage == 2) ? 0 : stage + 1;                                 \
    }

// =====================================================================
// Fused QKV GEMM: Q/K 1-chain, V 2-chain.
// =====================================================================
__global__ void __launch_bounds__(256, 1) gemm_qkv_kernel()
{
    extern __shared__ char smc[];
    const uint32_t smb = smem_u32(smc);
    const bool twoc = (blockIdx.x >= (DIM + KVD) / 128);

    GEMM_BODY(g_xh, g_wh, g_wl, DIM, twoc)

    const int gp = lane >> 2, t4 = lane & 3;
#pragma unroll
    for (int mt = 0; mt < 2; mt++) {
#pragma unroll
        for (int nt = 0; nt < 8; nt++) {
            int row  = bm + wm * 32 + mt * 16 + gp;
            int gcol = bn + wn * 64 + nt * 8 + t4 * 2;
            float c0 = acc[mt][nt][0] * WUNSCALE, c1 = acc[mt][nt][1] * WUNSCALE;
            float c2 = acc[mt][nt][2] * WUNSCALE, c3 = acc[mt][nt][3] * WUNSCALE;
            if (gcol < DIM) {
                *(float2*)&g_qraw[(size_t)row * DIM + gcol]       = make_float2(c0, c1);
                *(float2*)&g_qraw[(size_t)(row + 8) * DIM + gcol] = make_float2(c2, c3);
            } else if (gcol < DIM + KVD) {
                int cc = gcol - DIM;
                *(float2*)&g_kraw[(size_t)row * KVD + cc]       = make_float2(c0, c1);
                *(float2*)&g_kraw[(size_t)(row + 8) * KVD + cc] = make_float2(c2, c3);
            } else {
                int cc = gcol - DIM - KVD;
                float l0, l1;
                uint32_t h = packh2(c0, c1, &l0, &l1);
                *(uint32_t*)&g_vh[(size_t)row * KVD + cc] = h;
                *(uint32_t*)&g_vl[(size_t)row * KVD + cc] = packh2n(l0, l1);
                h = packh2(c2, c3, &l0, &l1);
                *(uint32_t*)&g_vh[(size_t)(row + 8) * KVD + cc] = h;
                *(uint32_t*)&g_vl[(size_t)(row + 8) * KVD + cc] = packh2n(l0, l1);
            }
        }
    }
}

// =====================================================================
// Wo GEMM (1-chain)
// =====================================================================
__global__ void __launch_bounds__(256, 1) gemm_wo_kernel(
    const __half* __restrict__ Bhp, float* __restrict__ C)
{
    extern __shared__ char smc[];
    const uint32_t smb = smem_u32(smc);

    GEMM_BODY(g_yh, Bhp, Bhp, DIM, false)

    const int gp = lane >> 2, t4 = lane & 3;
#pragma unroll
    for (int mt = 0; mt < 2; mt++) {
#pragma unroll
        for (int nt = 0; nt < 8; nt++) {
            int row = bm + wm * 32 + mt * 16 + gp;
            int col = bn + wn * 64 + nt * 8 + t4 * 2;
            *(float2*)&C[(size_t)row * DIM + col] =
                make_float2(acc[mt][nt][0] * WUNSCALE, acc[mt][nt][1] * WUNSCALE);
            *(float2*)&C[(size_t)(row + 8) * DIM + col] =
                make_float2(acc[mt][nt][2] * WUNSCALE, acc[mt][nt][3] * WUNSCALE);
        }
    }
}

// =====================================================================
// Fused RMSNorm + RoPE (unchanged)
// =====================================================================
__global__ void __launch_bounds__(128) normrope_kernel(const float* __restrict__ q_gain)
{
    const int bs = blockIdx.x;
    const int b  = bs >> 11;
    const int s  = bs & (SS - 1);
    const int hh = blockIdx.y;
    const int i  = threadIdx.x;
    const bool isq = (hh < NH);

    const float* src = isq
        ? &g_qraw[((size_t)bs * NH + hh) * HD]
        : &g_kraw[((size_t)bs * NKVH + (hh - NH)) * HD];

    float v = src[i];

    float ss = v * v;
#pragma unroll
    for (int o = 16; o > 0; o >>= 1) ss += __shfl_xor_sync(0xffffffffu, ss, o);
    __shared__ float wsum[4];
    if ((i & 31) == 0) wsum[i >> 5] = ss;
    __syncthreads();
    float tot = wsum[0] + wsum[1] + wsum[2] + wsum[3];
    float rn = rsqrtf(tot * (1.0f / HD) + EPSV);

    __shared__ float sh[HD];
    sh[i] = v * rn;
    __syncthreads();

    const int ii = i & 63;
    double inv_freq = pow(10000.0, -(double)ii / 64.0);
    double cd, sd;
    sincos((double)s * inv_freq, &cd, &sd);
    const float c = (float)cd, sn = (float)sd;

    float x1 = sh[ii], x2 = sh[ii + 64];
    float outv = (i < 64) ? (x1 * c - x2 * sn) : (x1 * sn + x2 * c);

    if (isq) {
        outv *= q_gain[hh] * QSC;
        g_qh[(((size_t)b * NH + hh) * SS + s) * HD + i] = __float2half_rn(outv);
    } else {
        size_t o = (((size_t)b * NKVH + (hh - NH)) * SS + s) * HD + i;
        __half h = __float2half_rn(outv);
        g_kh[o] = h;
        g_kl[o] = __float2half_rn(outv - __half2float(h));
    }
}

// =====================================================================
// Flash sliding-window attention (unchanged; measured 119 us)
// =====================================================================
#define AQSTR 136
#define APSTR 72
#define AQ  0
#define AKH (64 * AQSTR)
#define AKL (2 * 64 * AQSTR)
#define AVH (3 * 64 * AQSTR)
#define AVL (4 * 64 * AQSTR)
#define AP  (5 * 64 * AQSTR)
#define ATTN_SMEM_BYTES ((AP + 64 * APSTR) * 2)   // 96256

__global__ void __launch_bounds__(256, 2) attn_kernel()
{
    extern __shared__ __half sma[];
    const uint32_t smb = smem_u32(sma);
    __shared__ float rowsumP[64][4];
    __shared__ float rinv[64];

    const int tid  = threadIdx.x;
    const int wid  = tid >> 5;
    const int lane = tid & 31;
    const int wm   = wid & 1;
    const int wn   = wid >> 1;
    const int gp   = lane >> 2;
    const int t4   = lane & 3;

    const int qt  = blockIdx.x;
    const int h   = blockIdx.y;
    const int b   = blockIdx.z;
    const int kvh = h >> 2;
    const int qs0 = qt * 64;
    const int t0  = max(0, qs0 - (WIN - 1));
    const int L   = qs0 + 64 - t0;
    const int nchunks = (L + 63) >> 6;

    const __half* Qh = g_qh + (((size_t)b * NH + h) * SS + qs0) * HD;
    const __half* Kh = g_kh + ((size_t)b * NKVH + kvh) * SS * HD;
    const __half* Kl = g_kl + ((size_t)b * NKVH + kvh) * SS * HD;
    const __half* Vh = g_vh + ((size_t)(b * SS)) * KVD + kvh * HD;
    const __half* Vl = g_vl + ((size_t)(b * SS)) * KVD + kvh * HD;

#pragma unroll
    for (int it = 0; it < 4; it++) {
        int idx = tid + it * 256;
        int row = idx >> 4;
        int h8  = (idx & 15) * 8;
        *(uint4*)&sma[AQ + row * AQSTR + h8] = *(const uint4*)&Qh[(size_t)row * HD + h8];
    }
    rowsumP[tid >> 2][tid & 3] = 0.f;

    auto issueK = [&](int kt) {
#pragma unroll
        for (int it = 0; it < 4; it++) {
            int idx = tid + it * 256;
            int n   = idx >> 4;
            int h8  = (idx & 15) * 8;
            int j   = kt + n;
            int sz  = (j < L) ? 16 : 0;
            int jc  = (j < L) ? j : 0;
            cp16z(smb + (AKH + n * AQSTR + h8) * 2, Kh + (size_t)(t0 + jc) * HD + h8, sz);
            cp16z(smb + (AKL + n * AQSTR + h8) * 2, Kl + (size_t)(t0 + jc) * HD + h8, sz);
        }
    };
    auto issueV = [&](int kt) {
#pragma unroll
        for (int it = 0; it < 4; it++) {
            int idx = tid + it * 256;
            int n   = idx >> 4;
            int h8  = (idx & 15) * 8;
            int j   = kt + n;
            int sz  = (j < L) ? 16 : 0;
            int jc  = (j < L) ? j : 0;
            cp16z(smb + (AVH + n * AQSTR + h8) * 2, Vh + (size_t)(t0 + jc) * KVD + h8, sz);
            cp16z(smb + (AVL + n * AQSTR + h8) * 2, Vl + (size_t)(t0 + jc) * KVD + h8, sz);
        }
    };

    issueK(0);
    CP_COMMIT();

    float oacc[2][4][4];
#pragma unroll
    for (int mt = 0; mt < 2; mt++)
#pragma unroll
        for (int nt = 0; nt < 4; nt++)
#pragma unroll
            for (int r = 0; r < 4; r++) oacc[mt][nt][r] = 0.f;

    const int a_mrow = lane & 15;
    const int a_koff = (lane >> 4) << 3;
    const int b_row4 = (lane & 7) + ((lane >> 4) & 1) * 8;
    const int b_koff = ((lane >> 3) & 1) << 3;
    const int v_trow = ((lane >> 3) & 1) * 8 + (lane & 7);
    const int v_tcol = ((lane >> 4) & 1) * 8;

    for (int ck = 0; ck < nchunks; ck++) {
        const int kt = ck * 64;

        CP_WAIT0();
        __syncthreads();
        issueV(kt);
        CP_COMMIT();

        float sc[2][2][4];
#pragma unroll
        for (int mt = 0; mt < 2; mt++)
#pragma unroll
            for (int nt = 0; nt < 2; nt++)
#pragma unroll
                for (int r = 0; r < 4; r++) sc[mt][nt][r] = 0.f;

#pragma unroll
        for (int ks = 0; ks < 8; ks++) {
            uint32_t ah[2][4];
#pragma unroll
            for (int mt = 0; mt < 2; mt++)
                ldsm_x4(ah[mt], smb + (AQ + (wm * 32 + mt * 16 + a_mrow) * AQSTR
                                       + ks * 16 + a_koff) * 2);
            uint32_t bh[4], bl[4];
            uint32_t br = smb + (AKH + (wn * 16 + b_row4) * AQSTR
                                 + ks * 16 + b_koff) * 2;
            ldsm_x4(bh, br);
            ldsm_x4(bl, br + (AKL - AKH) * 2);
#pragma unroll
            for (int nt = 0; nt < 2; nt++)
#pragma unroll
                for (int mt = 0; mt < 2; mt++) {
                    mma_f16(sc[mt][nt], ah[mt], &bh[nt * 2]);
                    mma_f16(sc[mt][nt], ah[mt], &bl[nt * 2]);
                }
        }

        CP_WAIT0();
        __syncthreads();
        if (ck + 1 < nchunks) issueK(kt + 64);
        CP_COMMIT();

#pragma unroll
        for (int mt = 0; mt < 2; mt++) {
            const int r0l = wm * 32 + mt * 16 + gp;
            const int r0  = qs0 + r0l;
            float rs0 = 0.f, rs1 = 0.f;
#pragma unroll
            for (int nt = 0; nt < 2; nt++) {
                int jl = wn * 16 + nt * 8 + t4 * 2;
                int tg = t0 + kt + jl;
                bool in0 = (kt + jl) < L, in1 = (kt + jl + 1) < L;
                float e0 = (in0 && tg <= r0 && tg + WIN > r0)
                               ? exp2f(sc[mt][nt][0] - EOFF) : 0.f;
                float e1 = (in1 && tg + 1 <= r0 && tg + 1 + WIN > r0)
                               ? exp2f(sc[mt][nt][1] - EOFF) : 0.f;
                float e2 = (in0 && tg <= r0 + 8 && tg + WIN > r0 + 8)
                               ? exp2f(sc[mt][nt][2] - EOFF) : 0.f;
                float e3 = (in1 && tg + 1 <= r0 + 8 && tg + 1 + WIN > r0 + 8)
                               ? exp2f(sc[mt][nt][3] - EOFF) : 0.f;
                *(uint32_t*)&sma[AP + r0l * APSTR + jl]       = packh2n(e0, e1);
                *(uint32_t*)&sma[AP + (r0l + 8) * APSTR + jl] = packh2n(e2, e3);
                rs0 += e0 + e1;
                rs1 += e2 + e3;
            }
            rs0 += __shfl_xor_sync(0xffffffffu, rs0, 1);
            rs0 += __shfl_xor_sync(0xffffffffu, rs0, 2);
            rs1 += __shfl_xor_sync(0xffffffffu, rs1, 1);
            rs1 += __shfl_xor_sync(0xffffffffu, rs1, 2);
            if (t4 == 0) {
                rowsumP[r0l][wn]     += rs0;
                rowsumP[r0l + 8][wn] += rs1;
            }
        }
        __syncthreads();

#pragma unroll
        for (int ks2 = 0; ks2 < 4; ks2++) {
            uint32_t ph[2][4];
#pragma unroll
            for (int mt = 0; mt < 2; mt++)
                ldsm_x4(ph[mt], smb + (AP + (wm * 32 + mt * 16 + a_mrow) * APSTR
                                       + ks2 * 16 + a_koff) * 2);
#pragma unroll
            for (int vt2 = 0; vt2 < 2; vt2++) {
                uint32_t vr = smb + (AVH + (ks2 * 16 + v_trow) * AQSTR
                                     + wn * 32 + vt2 * 16 + v_tcol) * 2;
                uint32_t vh4[4], vl4[4];
                ldsm_x4_t(vh4, vr);
                ldsm_x4_t(vl4, vr + (AVL - AVH) * 2);
#pragma unroll
                for (int sub = 0; sub < 2; sub++)
#pragma unroll
                    for (int mt = 0; mt < 2; mt++) {
                        float* a4 = oacc[mt][vt2 * 2 + sub];
                        mma_f16(a4, ph[mt], &vh4[sub * 2]);
                        mma_f16(a4, ph[mt], &vl4[sub * 2]);
                    }
            }
        }
    }
    __syncthreads();

    if (tid < 64)
        rinv[tid] = 1.0f / (rowsumP[tid][0] + rowsumP[tid][1] +
                            rowsumP[tid][2] + rowsumP[tid][3]);
    __syncthreads();

#pragma unroll
    for (int mt = 0; mt < 2; mt++) {
        const int r0l = wm * 32 + mt * 16 + gp;
        const float ri0 = rinv[r0l];
        const float ri1 = rinv[r0l + 8];
#pragma unroll
        for (int nt = 0; nt < 4; nt++) {
            int d = wn * 32 + nt * 8 + t4 * 2;
            size_t y0 = ((size_t)(b * SS + qs0 + r0l) * NH + h) * HD + d;
            size_t y1 = ((size_t)(b * SS + qs0 + r0l + 8) * NH + h) * HD + d;
            *(uint32_t*)&g_yh[y0] = packh2n(oacc[mt][nt][0] * ri0, oacc[mt][nt][1] * ri0);
            *(uint32_t*)&g_yh[y1] = packh2n(oacc[mt][nt][2] * ri1, oacc[mt][nt][3] * ri1);
        }
    }
}

// =====================================================================
// launch
// =====================================================================
extern "C" void kernel_launch(void* const* d_in, const int* in_sizes, int n_in,
                              void* d_out, int out_size)
{
    float* out = (float*)d_out;

    const float* x  = nullptr;
    const float* qg = nullptr;
    const float* big[2] = {nullptr, nullptr};
    const float* kv [2] = {nullptr, nullptr};
    int nb = 0, nk = 0;

    for (int i = 0; i < n_in; i++) {
        long s = in_sizes[i];
        const float* p = (const float*)d_in[i];
        if      (s == (long)BB * SS * DIM)        x = p;
        else if (s == (long)DIM * DIM)            { if (nb < 2) big[nb++] = p; }
        else if (s == (long)KVD * DIM)            { if (nk < 2) kv[nk++] = p; }
        else if (s == (long)NH)                   qg = p;
    }
    const float* Wq = big[0];
    const float* Wo = big[1];
    const float* Wk = kv[0];
    const float* Wv = kv[1];

    __half *xh, *wh, *wl;
    cudaGetSymbolAddress((void**)&xh, g_xh);
    cudaGetSymbolAddress((void**)&wh, g_wh);
    cudaGetSymbolAddress((void**)&wl, g_wl);

    cudaFuncSetAttribute(gemm_qkv_kernel,
                         cudaFuncAttributeMaxDynamicSharedMemorySize, GEMM_SMEM);
    cudaFuncSetAttribute(gemm_wo_kernel,
                         cudaFuncAttributeMaxDynamicSharedMemorySize, GEMM_SMEM);
    cudaFuncSetAttribute(attn_kernel,
                         cudaFuncAttributeMaxDynamicSharedMemorySize, ATTN_SMEM_BYTES);

    const size_t off_o = (size_t)(DIM + KVD + KVD) * DIM;

    conv_x_kernel<<<4096, 256>>>((const float4*)x, (uint2*)xh, (long)M_TOT * DIM / 4);
    split_w_all_kernel<<<4096, 256>>>((const float4*)Wq, (const float4*)Wk,
                                      (const float4*)Wv, (const float4*)Wo,
                                      (uint2*)wh, (uint2*)wl);

    // fused QKV projection (BK=64, single-sync mainloop)
    gemm_qkv_kernel<<<dim3(NQKV / 128, M_TOT / 128), 256, GEMM_SMEM>>>();

    // rmsnorm + rope
    normrope_kernel<<<dim3(BB * SS, NH + NKVH), 128>>>(qg);

    // attention
    attn_kernel<<<dim3(SS / 64, NH, BB), 256, ATTN_SMEM_BYTES>>>();

    // output projection (1-chain, BK=64)
    gemm_wo_kernel<<<dim3(DIM / 128, M_TOT / 128), 256, GEMM_SMEM>>>(
        wh + off_o, out);
}